// round 1
// baseline (speedup 1.0000x reference)
#include <cuda_runtime.h>

// Problem constants (fixed by the reference)
#define NN 100000
#define EE 3200000

// Scratch: __device__ globals (no allocation allowed in kernel_launch)
__device__ float g_deg[NN];
__device__ float g_dinv[NN];
__device__ float g_a[NN];
__device__ float g_b[NN];
__device__ float g_sa[NN];
__device__ float g_sb[NN];
__device__ float g_q[NN];
__device__ float g_t[NN];

// ---------------------------------------------------------------------------
// K1: init — deg starts at 1 (self-loop), accumulators at 0
__global__ void k_init(int n) {
    int i = blockIdx.x * blockDim.x + threadIdx.x;
    if (i < n) {
        g_deg[i] = 1.0f;
        g_sa[i]  = 0.0f;
        g_sb[i]  = 0.0f;
        g_t[i]   = 0.0f;
    }
}

// K2: degree count over edge destinations (col), int4-vectorized
__global__ void k_deg(const int4* __restrict__ col4, int e4) {
    int i = blockIdx.x * blockDim.x + threadIdx.x;
    if (i < e4) {
        int4 c = col4[i];
        atomicAdd(&g_deg[c.x], 1.0f);
        atomicAdd(&g_deg[c.y], 1.0f);
        atomicAdd(&g_deg[c.z], 1.0f);
        atomicAdd(&g_deg[c.w], 1.0f);
    }
}

// K3: per-node dinv = rsqrt(deg); a = dinv*x0; b = dinv*x1
__global__ void k_node1(const float* __restrict__ x, int n) {
    int i = blockIdx.x * blockDim.x + threadIdx.x;
    if (i < n) {
        float d = g_deg[i];           // >= 1 always (self-loop)
        float dinv = rsqrtf(d);
        float2 xi = ((const float2*)x)[i];
        g_dinv[i] = dinv;
        g_a[i] = dinv * xi.x;
        g_b[i] = dinv * xi.y;
    }
}

// K4: layer-1 edge scatter — two scalar coefficients per edge
__global__ void k_scatter1(const int4* __restrict__ row4,
                           const int4* __restrict__ col4, int e4) {
    int i = blockIdx.x * blockDim.x + threadIdx.x;
    if (i < e4) {
        int4 r = row4[i];
        int4 c = col4[i];
        float a0 = g_a[r.x], b0 = g_b[r.x];
        float a1 = g_a[r.y], b1 = g_b[r.y];
        float a2 = g_a[r.z], b2 = g_b[r.z];
        float a3 = g_a[r.w], b3 = g_b[r.w];
        atomicAdd(&g_sa[c.x], a0); atomicAdd(&g_sb[c.x], b0);
        atomicAdd(&g_sa[c.y], a1); atomicAdd(&g_sb[c.y], b1);
        atomicAdd(&g_sa[c.z], a2); atomicAdd(&g_sb[c.z], b2);
        atomicAdd(&g_sa[c.w], a3); atomicAdd(&g_sb[c.w], b3);
    }
}

// K5: per-node — reconstruct h1 (64-wide), relu, dot with W2 -> q = dinv * p
__global__ void k_node2(const float* __restrict__ W1,
                        const float* __restrict__ b1,
                        const float* __restrict__ W2, int n) {
    __shared__ float sW10[64], sW11[64], sB1[64], sW2[64];
    int t = threadIdx.x;
    if (t < 64) {
        sW10[t] = W1[t];        // W1[0][j]
        sW11[t] = W1[64 + t];   // W1[1][j]
        sB1[t]  = b1[t];
        sW2[t]  = W2[t];        // W2[j][0]
    }
    __syncthreads();
    int i = blockIdx.x * blockDim.x + t;
    if (i < n) {
        float dinv = g_dinv[i];
        float ca = g_sa[i] + g_a[i];   // neighbor sum + self-loop term
        float cb = g_sb[i] + g_b[i];
        float p = 0.0f;
        #pragma unroll
        for (int j = 0; j < 64; j++) {
            float h = fmaf(dinv, fmaf(ca, sW10[j], cb * sW11[j]), sB1[j]);
            h = fmaxf(h, 0.0f);
            p = fmaf(h, sW2[j], p);
        }
        g_q[i] = dinv * p;
    }
}

// K6: layer-2 edge scatter — one scalar per edge
__global__ void k_scatter2(const int4* __restrict__ row4,
                           const int4* __restrict__ col4, int e4) {
    int i = blockIdx.x * blockDim.x + threadIdx.x;
    if (i < e4) {
        int4 r = row4[i];
        int4 c = col4[i];
        atomicAdd(&g_t[c.x], g_q[r.x]);
        atomicAdd(&g_t[c.y], g_q[r.y]);
        atomicAdd(&g_t[c.z], g_q[r.z]);
        atomicAdd(&g_t[c.w], g_q[r.w]);
    }
}

// K7: final — out = b2 + dinv * (t + q)
__global__ void k_final(const float* __restrict__ b2,
                        float* __restrict__ out, int n) {
    int i = blockIdx.x * blockDim.x + threadIdx.x;
    if (i < n) {
        out[i] = fmaf(g_dinv[i], g_t[i] + g_q[i], b2[0]);
    }
}

extern "C" void kernel_launch(void* const* d_in, const int* in_sizes, int n_in,
                              void* d_out, int out_size) {
    const float* x   = (const float*)d_in[0];   // [N,2]
    const int*   ei  = (const int*)d_in[1];     // [2,E]
    const float* W1  = (const float*)d_in[2];   // [2,64]
    const float* b1  = (const float*)d_in[3];   // [64]
    const float* W2  = (const float*)d_in[4];   // [64,1]
    const float* b2  = (const float*)d_in[5];   // [1]
    float* out = (float*)d_out;                 // [N]

    const int n = NN;
    const int e4 = EE / 4;
    const int4* row4 = (const int4*)ei;
    const int4* col4 = (const int4*)(ei + EE);

    const int TB = 256;
    const int gN = (n + TB - 1) / TB;
    const int gE = (e4 + TB - 1) / TB;

    k_init    <<<gN, TB>>>(n);
    k_deg     <<<gE, TB>>>(col4, e4);
    k_node1   <<<gN, TB>>>(x, n);
    k_scatter1<<<gE, TB>>>(row4, col4, e4);
    k_node2   <<<gN, TB>>>(W1, b1, W2, n);
    k_scatter2<<<gE, TB>>>(row4, col4, e4);
    k_final   <<<gN, TB>>>(b2, out, n);
}

// round 2
// speedup vs baseline: 1.2619x; 1.2619x over previous
#include <cuda_runtime.h>

#define NN 100000
#define EE 3200000

// Scratch (__device__ globals; no allocation allowed)
__device__ float  g_deg[NN];
__device__ float  g_dinv[NN];
__device__ float2 g_ab[NN];    // (dinv*x0, dinv*x1) per node, interleaved
__device__ float2 g_sab[NN];   // scatter accumulators, interleaved
__device__ float  g_q[NN];
__device__ float  g_t[NN];

// 64-bit vector reduction: one L2 atomic op for (a,b)
__device__ __forceinline__ void red_add_v2(float2* addr, float a, float b) {
    asm volatile("red.global.add.v2.f32 [%0], {%1, %2};"
                 :: "l"(addr), "f"(a), "f"(b) : "memory");
}

// K1: init — deg=1 (self-loop), zero accumulators
__global__ void k_init(int n) {
    int i = blockIdx.x * blockDim.x + threadIdx.x;
    if (i < n) {
        g_deg[i] = 1.0f;
        g_sab[i] = make_float2(0.0f, 0.0f);
        g_t[i]   = 0.0f;
    }
}

// K2: degree count (col only), int4-vectorized, 2 vec-reads per thread
__global__ void k_deg(const int4* __restrict__ col4, int e4) {
    int i = (blockIdx.x * blockDim.x + threadIdx.x) * 2;
    #pragma unroll
    for (int u = 0; u < 2; u++) {
        int idx = i + u;
        if (idx < e4) {
            int4 c = __ldg(&col4[idx]);
            atomicAdd(&g_deg[c.x], 1.0f);
            atomicAdd(&g_deg[c.y], 1.0f);
            atomicAdd(&g_deg[c.z], 1.0f);
            atomicAdd(&g_deg[c.w], 1.0f);
        }
    }
}

// K3: per-node dinv and (a,b)
__global__ void k_node1(const float* __restrict__ x, int n) {
    int i = blockIdx.x * blockDim.x + threadIdx.x;
    if (i < n) {
        float dinv = rsqrtf(g_deg[i]);
        float2 xi = ((const float2*)x)[i];
        g_dinv[i] = dinv;
        g_ab[i] = make_float2(dinv * xi.x, dinv * xi.y);
    }
}

// K4: layer-1 edge scatter — one 64b gather + one 64b vector red per edge
__global__ void k_scatter1(const int4* __restrict__ row4,
                           const int4* __restrict__ col4, int e4) {
    int i = (blockIdx.x * blockDim.x + threadIdx.x) * 2;
    #pragma unroll
    for (int u = 0; u < 2; u++) {
        int idx = i + u;
        if (idx < e4) {
            int4 r = __ldg(&row4[idx]);
            int4 c = __ldg(&col4[idx]);
            float2 v0 = __ldg(&g_ab[r.x]);
            float2 v1 = __ldg(&g_ab[r.y]);
            float2 v2 = __ldg(&g_ab[r.z]);
            float2 v3 = __ldg(&g_ab[r.w]);
            red_add_v2(&g_sab[c.x], v0.x, v0.y);
            red_add_v2(&g_sab[c.y], v1.x, v1.y);
            red_add_v2(&g_sab[c.z], v2.x, v2.y);
            red_add_v2(&g_sab[c.w], v3.x, v3.y);
        }
    }
}

// K5: per-node — reconstruct h1 (64-wide), relu, dot W2 -> q = dinv * p
__global__ void k_node2(const float* __restrict__ W1,
                        const float* __restrict__ b1,
                        const float* __restrict__ W2, int n) {
    __shared__ float sW10[64], sW11[64], sB1[64], sW2[64];
    int t = threadIdx.x;
    if (t < 64) {
        sW10[t] = W1[t];
        sW11[t] = W1[64 + t];
        sB1[t]  = b1[t];
        sW2[t]  = W2[t];
    }
    __syncthreads();
    int i = blockIdx.x * blockDim.x + t;
    if (i < n) {
        float dinv = g_dinv[i];
        float2 self = g_ab[i];
        float2 acc  = g_sab[i];
        float ca = acc.x + self.x;      // neighbor sum + self-loop
        float cb = acc.y + self.y;
        float p = 0.0f;
        #pragma unroll
        for (int j = 0; j < 64; j++) {
            float h = fmaf(dinv, fmaf(ca, sW10[j], cb * sW11[j]), sB1[j]);
            h = fmaxf(h, 0.0f);
            p = fmaf(h, sW2[j], p);
        }
        g_q[i] = dinv * p;
    }
}

// K6: layer-2 edge scatter — one 32b gather + one 32b red per edge
__global__ void k_scatter2(const int4* __restrict__ row4,
                           const int4* __restrict__ col4, int e4) {
    int i = (blockIdx.x * blockDim.x + threadIdx.x) * 2;
    #pragma unroll
    for (int u = 0; u < 2; u++) {
        int idx = i + u;
        if (idx < e4) {
            int4 r = __ldg(&row4[idx]);
            int4 c = __ldg(&col4[idx]);
            float q0 = __ldg(&g_q[r.x]);
            float q1 = __ldg(&g_q[r.y]);
            float q2 = __ldg(&g_q[r.z]);
            float q3 = __ldg(&g_q[r.w]);
            atomicAdd(&g_t[c.x], q0);
            atomicAdd(&g_t[c.y], q1);
            atomicAdd(&g_t[c.z], q2);
            atomicAdd(&g_t[c.w], q3);
        }
    }
}

// K7: final
__global__ void k_final(const float* __restrict__ b2,
                        float* __restrict__ out, int n) {
    int i = blockIdx.x * blockDim.x + threadIdx.x;
    if (i < n) {
        out[i] = fmaf(g_dinv[i], g_t[i] + g_q[i], b2[0]);
    }
}

extern "C" void kernel_launch(void* const* d_in, const int* in_sizes, int n_in,
                              void* d_out, int out_size) {
    const float* x   = (const float*)d_in[0];
    const int*   ei  = (const int*)d_in[1];
    const float* W1  = (const float*)d_in[2];
    const float* b1  = (const float*)d_in[3];
    const float* W2  = (const float*)d_in[4];
    const float* b2  = (const float*)d_in[5];
    float* out = (float*)d_out;

    const int n = NN;
    const int e4 = EE / 4;
    const int4* row4 = (const int4*)ei;
    const int4* col4 = (const int4*)(ei + EE);

    const int TB = 256;
    const int gN = (n + TB - 1) / TB;
    const int gE2 = (e4 / 2 + TB - 1) / TB;   // 2 int4 per thread

    k_init    <<<gN, TB>>>(n);
    k_deg     <<<gE2, TB>>>(col4, e4);
    k_node1   <<<gN, TB>>>(x, n);
    k_scatter1<<<gE2, TB>>>(row4, col4, e4);
    k_node2   <<<gN, TB>>>(W1, b1, W2, n);
    k_scatter2<<<gE2, TB>>>(row4, col4, e4);
    k_final   <<<gN, TB>>>(b2, out, n);
}